// round 3
// baseline (speedup 1.0000x reference)
#include <cuda_runtime.h>
#include <stdint.h>

#define NROW 16384
#define KC 32
#define NCHUNK (NROW / KC)            /* 512 */
#define STG 4
#define STAGE_BYTES 32768             /* A 16KB + B 16KB */
#define BIG_SMEM (STG * STAGE_BYTES)  /* 131072 */
#define PREP_SMEM ((64 * 64 + 128 * 132) * 4)

__device__ float g_Tt[128 * NROW];    /* B operand, K-major, tf32-rounded */
__device__ float g_X[NROW * 128];     /* layer activations */

__device__ __forceinline__ float eluf(float x) { return x > 0.f ? x : expm1f(x); }
__device__ __forceinline__ uint32_t swz(uint32_t x) { return x ^ ((x >> 3) & 0x70); }

__device__ __forceinline__ uint32_t smem_u32(const void* p) {
    uint32_t a;
    asm("{ .reg .u64 t; cvta.to.shared.u64 t, %1; cvt.u32.u64 %0, t; }" : "=r"(a) : "l"(p));
    return a;
}
__device__ __forceinline__ void cp_async16(uint32_t dst, const void* src) {
    asm volatile("cp.async.cg.shared.global [%0], [%1], 16;" :: "r"(dst), "l"(src) : "memory");
}
__device__ __forceinline__ void ldsm_x4(uint32_t* r, uint32_t addr) {
    asm volatile("ldmatrix.sync.aligned.m8n8.x4.shared.b16 {%0,%1,%2,%3}, [%4];"
                 : "=r"(r[0]), "=r"(r[1]), "=r"(r[2]), "=r"(r[3]) : "r"(addr));
}
__device__ __forceinline__ void mma_tf32(float* c, const uint32_t* a, const uint32_t* b) {
    asm volatile(
        "mma.sync.aligned.m16n8k8.row.col.f32.tf32.tf32.f32 "
        "{%0,%1,%2,%3}, {%4,%5,%6,%7}, {%8,%9}, {%0,%1,%2,%3};"
        : "+f"(c[0]), "+f"(c[1]), "+f"(c[2]), "+f"(c[3])
        : "r"(a[0]), "r"(a[1]), "r"(a[2]), "r"(a[3]), "r"(b[0]), "r"(b[1]));
}
__device__ __forceinline__ float tf32r(float x) {
    uint32_t u;
    asm("cvt.rna.tf32.f32 %0, %1;" : "=r"(u) : "f"(x));
    return __uint_as_float(u);
}

/* Tt[j][k] = sum_d f(src[k][d(+64)]) * W[d][j&63]; output tf32-rounded */
__global__ __launch_bounds__(512) void gcn_prep(const float* __restrict__ Xin,
                                                const float* __restrict__ W,
                                                int apply_elu, int use_gx) {
    extern __shared__ float sm[];
    float* sW = sm;
    float* sXT = sm + 64 * 64;
    const float* src = use_gx ? (const float*)g_X : Xin;
    int tid = threadIdx.x;
    int k0 = blockIdx.x * 128;

    for (int l = tid; l < 64 * 64; l += 512) sW[l] = W[l];
    #pragma unroll
    for (int it = 0; it < 32; ++it) {
        int l = it * 512 + tid;
        int k = l >> 7, d = l & 127;
        float v = src[(size_t)(k0 + k) * 128 + d];
        if (apply_elu) v = eluf(v);
        sXT[d * 132 + k] = v;
    }
    __syncthreads();

    int warp = tid >> 5, lane = tid & 31;
    int k = lane * 4;
    for (int jp = warp; jp < 64; jp += 16) {
        float4 a0 = make_float4(0.f, 0.f, 0.f, 0.f);
        float4 a1 = make_float4(0.f, 0.f, 0.f, 0.f);
        #pragma unroll 16
        for (int d = 0; d < 64; ++d) {
            float w = sW[d * 64 + jp];
            float4 xs = *(const float4*)&sXT[d * 132 + k];
            float4 xu = *(const float4*)&sXT[(64 + d) * 132 + k];
            a0.x = fmaf(xs.x, w, a0.x); a0.y = fmaf(xs.y, w, a0.y);
            a0.z = fmaf(xs.z, w, a0.z); a0.w = fmaf(xs.w, w, a0.w);
            a1.x = fmaf(xu.x, w, a1.x); a1.y = fmaf(xu.y, w, a1.y);
            a1.z = fmaf(xu.z, w, a1.z); a1.w = fmaf(xu.w, w, a1.w);
        }
        a0.x = tf32r(a0.x); a0.y = tf32r(a0.y); a0.z = tf32r(a0.z); a0.w = tf32r(a0.w);
        a1.x = tf32r(a1.x); a1.y = tf32r(a1.y); a1.z = tf32r(a1.z); a1.w = tf32r(a1.w);
        *(float4*)&g_Tt[(size_t)jp * NROW + k0 + k] = a0;
        *(float4*)&g_Tt[(size_t)(jp + 64) * NROW + k0 + k] = a1;
    }
}

/* g_X[m][n] = elu( sum_k adj[m][k] * Tt[n][k] + bias[n&63] ), mma.sync tf32 */
__global__ __launch_bounds__(256, 1) void gcn_big(const float* __restrict__ adj,
                                                  const float* __restrict__ bias) {
    extern __shared__ char dsm[];
    uint32_t sb = smem_u32(dsm);
    int tid = threadIdx.x;
    int lane = tid & 31, wid = tid >> 5;
    int wm = wid & 3, wn = wid >> 2;      /* warp tile: 32(m) x 64(n) */
    int m0 = blockIdx.x * 128;
    int grp = lane >> 3, li = lane & 7;

    float acc[2][8][4];
    #pragma unroll
    for (int i = 0; i < 2; ++i)
        #pragma unroll
        for (int j = 0; j < 8; ++j)
            #pragma unroll
            for (int r = 0; r < 4; ++r) acc[i][j][r] = 0.f;

    const float* gA = adj + (size_t)m0 * NROW;
    const float* gB = g_Tt;

#define LOAD_STAGE(ii) do {                                                     \
    uint32_t st_ = sb + (uint32_t)((ii) & 3) * STAGE_BYTES;                     \
    int k0_ = (ii) * KC;                                                        \
    _Pragma("unroll")                                                           \
    for (int j_ = 0; j_ < 4; ++j_) {                                            \
        int v_ = j_ * 256 + tid;                                                \
        int row_ = v_ >> 3, seg_ = v_ & 7;                                      \
        uint32_t off_ = swz((uint32_t)(row_ * 128 + seg_ * 16));                \
        cp_async16(st_ + off_, gA + (size_t)row_ * NROW + k0_ + seg_ * 4);      \
        cp_async16(st_ + 16384u + off_, gB + (size_t)row_ * NROW + k0_ + seg_ * 4); \
    }                                                                           \
    asm volatile("cp.async.commit_group;" ::: "memory");                        \
} while (0)

    LOAD_STAGE(0); LOAD_STAGE(1); LOAD_STAGE(2);

    #pragma unroll 1
    for (int i = 0; i < NCHUNK; ++i) {
        asm volatile("cp.async.wait_group 2;" ::: "memory");
        __syncthreads();
        uint32_t sA = sb + (uint32_t)(i & 3) * STAGE_BYTES;
        uint32_t sB = sA + 16384u;
        #pragma unroll
        for (int t = 0; t < 4; ++t) {
            uint32_t a[2][4];
            #pragma unroll
            for (int mi = 0; mi < 2; ++mi) {
                int rowa = wm * 32 + mi * 16 + ((grp & 1) << 3) + li;
                int seg = t * 2 + (grp >> 1);
                ldsm_x4(a[mi], sA + swz((uint32_t)(rowa * 128 + seg * 16)));
            }
            #pragma unroll
            for (int mi = 0; mi < 2; ++mi)
                #pragma unroll
                for (int r = 0; r < 4; ++r)
                    asm("cvt.rna.tf32.f32 %0, %0;" : "+r"(a[mi][r]));
            uint32_t b[8][2];
            #pragma unroll
            for (int p = 0; p < 4; ++p) {
                int rowb = wn * 64 + p * 16 + ((grp >> 1) << 3) + li;
                int seg = t * 2 + (grp & 1);
                uint32_t r4[4];
                ldsm_x4(r4, sB + swz((uint32_t)(rowb * 128 + seg * 16)));
                b[2 * p][0] = r4[0]; b[2 * p][1] = r4[1];
                b[2 * p + 1][0] = r4[2]; b[2 * p + 1][1] = r4[3];
            }
            #pragma unroll
            for (int mi = 0; mi < 2; ++mi)
                #pragma unroll
                for (int ni = 0; ni < 8; ++ni)
                    mma_tf32(acc[mi][ni], a[mi], b[ni]);
        }
        if (i + 3 < NCHUNK) LOAD_STAGE(i + 3);
        else asm volatile("cp.async.commit_group;" ::: "memory");
    }

    /* epilogue: bias + elu, direct fragment store (8B vectors) */
    int col0 = wn * 64 + (lane & 3) * 2;
    int rbase = m0 + wm * 32 + (lane >> 2);
    #pragma unroll
    for (int mi = 0; mi < 2; ++mi)
        #pragma unroll
        for (int ni = 0; ni < 8; ++ni) {
            int col = col0 + ni * 8;
            float b0v = bias[col & 63], b1v = bias[(col + 1) & 63];
            int rlo = rbase + mi * 16;
            float2 v0 = make_float2(eluf(acc[mi][ni][0] + b0v), eluf(acc[mi][ni][1] + b1v));
            float2 v1 = make_float2(eluf(acc[mi][ni][2] + b0v), eluf(acc[mi][ni][3] + b1v));
            *(float2*)&g_X[(size_t)rlo * 128 + col] = v0;
            *(float2*)&g_X[(size_t)(rlo + 8) * 128 + col] = v1;
        }
#undef LOAD_STAGE
}

/* out[k][o] = sum_j g_X[k][j] * Wl[o][j] + bl[o] */
__global__ __launch_bounds__(256) void gcn_final(const float* __restrict__ Wl,
                                                 const float* __restrict__ bl,
                                                 float* __restrict__ out) {
    __shared__ float sWlT[128 * 32];
    int tid = threadIdx.x;
    for (int l = tid; l < 4096; l += 256) {
        int o = l >> 7, j = l & 127;
        sWlT[j * 32 + o] = Wl[l];
    }
    __syncthreads();
    int warp = tid >> 5, lane = tid & 31;
    int k0 = blockIdx.x * 128;
    float b = bl[lane];
    for (int r = warp; r < 128; r += 8) {
        const float* yrow = g_X + (size_t)(k0 + r) * 128;
        float acc = b;
        #pragma unroll 16
        for (int j = 0; j < 128; ++j)
            acc = fmaf(__ldg(&yrow[j]), sWlT[j * 32 + lane], acc);
        out[(size_t)(k0 + r) * 32 + lane] = acc;
    }
}

extern "C" void kernel_launch(void* const* d_in, const int* in_sizes, int n_in,
                              void* d_out, int out_size) {
    const float* z   = (const float*)d_in[0];
    const float* adj = (const float*)d_in[1];
    const float* W0  = (const float*)d_in[2];
    const float* b0  = (const float*)d_in[3];
    const float* W1  = (const float*)d_in[4];
    const float* b1  = (const float*)d_in[5];
    const float* Wl  = (const float*)d_in[6];
    const float* bl  = (const float*)d_in[7];
    float* out = (float*)d_out;

    cudaFuncSetAttribute(gcn_prep, cudaFuncAttributeMaxDynamicSharedMemorySize, PREP_SMEM);
    cudaFuncSetAttribute(gcn_big,  cudaFuncAttributeMaxDynamicSharedMemorySize, BIG_SMEM);

    gcn_prep<<<128, 512, PREP_SMEM>>>(z, W0, 1, 0);
    gcn_big <<<128, 256, BIG_SMEM>>>(adj, b0);
    gcn_prep<<<128, 512, PREP_SMEM>>>(z, W1, 0, 1);
    gcn_big <<<128, 256, BIG_SMEM>>>(adj, b1);
    gcn_final<<<128, 256>>>(Wl, bl, out);
}